// round 7
// baseline (speedup 1.0000x reference)
#include <cuda_runtime.h>
#include <cuda_bf16.h>
#include <cstdint>
#include <math.h>

// Problem constants (fixed by the dataset)
#define NA      50000
#define NP      10000
#define NE      400000
#define IN_DIM  512
#define FEAT    128
#define NH      8
#define OD      32
#define HD      256   // NH*OD

// ---------------- scratch (static device globals; no allocation) -----------
__device__ float g_z[(size_t)NA * HD];        // 51.2 MB
__device__ float g_ssrc[(size_t)NA * NH];
__device__ float g_eval[(size_t)NE * NH];
__device__ float g_vfeat[NH * FEAT];
__device__ int   g_counts[NP];
__device__ int   g_offsets[NP];
__device__ int   g_cursor[NP];
__device__ int   g_edge_sorted[NE];
// pre-split bf16 hi/lo operands
__device__ __nv_bfloat16 g_ahi[(size_t)NA * IN_DIM];
__device__ __nv_bfloat16 g_alo[(size_t)NA * IN_DIM];
__device__ __nv_bfloat16 g_bhi[(size_t)HD * IN_DIM];
__device__ __nv_bfloat16 g_blo[(size_t)HD * IN_DIM];

// ---------------- small utility kernels ------------------------------------
__global__ void k_zero_counts() {
    int t = blockIdx.x * blockDim.x + threadIdx.x;
    if (t < NP) g_counts[t] = 0;
}

__global__ void k_vfeat(const float* __restrict__ W_feat,
                        const float* __restrict__ W_attn) {
    int t = blockIdx.x * blockDim.x + threadIdx.x;
    if (t >= NH * FEAT) return;
    int h = t / FEAT, f = t % FEAT;
    float acc = 0.f;
#pragma unroll
    for (int d = 0; d < OD; ++d)
        acc += W_attn[2 * OD + d] * W_feat[(size_t)(h * OD + d) * FEAT + f];
    g_vfeat[t] = acc;
}

// ---------------- fp32 -> bf16 hi/lo split (bandwidth pass) -----------------
__global__ void __launch_bounds__(256) k_split(const float* __restrict__ src,
                                               __nv_bfloat16* __restrict__ hi,
                                               __nv_bfloat16* __restrict__ lo,
                                               int n4) {
    int t = blockIdx.x * blockDim.x + threadIdx.x;
    if (t >= n4) return;
    float4 v = ((const float4*)src)[t];
    __nv_bfloat16 hx = __float2bfloat16_rn(v.x);
    __nv_bfloat16 hy = __float2bfloat16_rn(v.y);
    __nv_bfloat16 hz = __float2bfloat16_rn(v.z);
    __nv_bfloat16 hw = __float2bfloat16_rn(v.w);
    __nv_bfloat162 h0 = __halves2bfloat162(hx, hy);
    __nv_bfloat162 h1 = __halves2bfloat162(hz, hw);
    __nv_bfloat162 l0 = __floats2bfloat162_rn(v.x - __bfloat162float(hx),
                                              v.y - __bfloat162float(hy));
    __nv_bfloat162 l1 = __floats2bfloat162_rn(v.z - __bfloat162float(hz),
                                              v.w - __bfloat162float(hw));
    uint2 hp = make_uint2(*(uint32_t*)&h0, *(uint32_t*)&h1);
    uint2 lp = make_uint2(*(uint32_t*)&l0, *(uint32_t*)&l1);
    ((uint2*)hi)[t] = hp;
    ((uint2*)lo)[t] = lp;
}

// ============ 3-term compensated bf16 GEMM (ldmatrix + cp.async) ============
// C[NA,256] = A @ B^T with A/B pre-split bf16 hi/lo:
//   D += Al*Bh + Ah*Bl + Ah*Bh
// One CTA: M=128, N=256 (full width), GBK=32, 3-stage cp.async pipeline.
// 512 threads = 16 warps (4m x 4n), warp tile 32x64, mma m16n8k16 + ldmatrix.
// SMEM rows: 32 bf16 = 64B padded to 80B -> conflict-free cp.async + ldmatrix.

#define GBK 32
#define ROWB 80                         // padded row stride in bytes
#define STG   (4 * 128 * ROWB + 2 * 128 * ROWB * 0 + 2 * 256 * ROWB * 0 + 0)
// explicit stage layout:
#define A_BYTES (128 * ROWB)            // 10240
#define B_BYTES (256 * ROWB)            // 20480
#define STAGE_B (2 * A_BYTES + 2 * B_BYTES)   // 61440
#define AHOF(s) ((s) * STAGE_B)
#define ALOF(s) (AHOF(s) + A_BYTES)
#define BHOF(s) (AHOF(s) + 2 * A_BYTES)
#define BLOF(s) (AHOF(s) + 2 * A_BYTES + B_BYTES)
#define NSTAGE 3
#define GEMM_SMEM (NSTAGE * STAGE_B)    // 184320
#define NTILE (IN_DIM / GBK)            // 16

__device__ __forceinline__ void cp16(uint32_t dst, const void* src, int srcsize) {
    asm volatile("cp.async.cg.shared.global [%0], [%1], 16, %2;\n"
                 :: "r"(dst), "l"(src), "r"(srcsize));
}
__device__ __forceinline__ uint32_t smem_u32(const void* p) {
    uint32_t a;
    asm("{ .reg .u64 t; cvta.to.shared.u64 t, %1; cvt.u32.u64 %0, t; }"
        : "=r"(a) : "l"(p));
    return a;
}

#define LDSM_X4(R0, R1, R2, R3, ADDR)                                         \
    asm volatile("ldmatrix.sync.aligned.m8n8.x4.shared.b16 {%0,%1,%2,%3}, [%4];" \
                 : "=r"(R0), "=r"(R1), "=r"(R2), "=r"(R3) : "r"(ADDR))

#define MMA_BF16(D, A0, A1, A2, A3, B0, B1)                                   \
    asm volatile(                                                             \
        "mma.sync.aligned.m16n8k16.row.col.f32.bf16.bf16.f32 "                \
        "{%0,%1,%2,%3}, {%4,%5,%6,%7}, {%8,%9}, {%0,%1,%2,%3};"               \
        : "+f"(D[0]), "+f"(D[1]), "+f"(D[2]), "+f"(D[3])                      \
        : "r"(A0), "r"(A1), "r"(A2), "r"(A3), "r"(B0), "r"(B1))

__global__ void __launch_bounds__(512, 1)
k_gemm_ldsm(const __nv_bfloat16* __restrict__ Ahg,
            const __nv_bfloat16* __restrict__ Alg,
            const __nv_bfloat16* __restrict__ Bhg,
            const __nv_bfloat16* __restrict__ Blg,
            float* __restrict__ C) {
    extern __shared__ char smem[];
    const uint32_t sb = smem_u32(smem);
    const int tid  = threadIdx.x;
    const int warp = tid >> 5, lane = tid & 31;
    const int g = lane >> 2, tg = lane & 3;
    const int wm = (warp >> 2) * 32;      // M offset of warp (4 warps in M)
    const int wn = (warp & 3) * 64;       // N offset of warp (4 warps in N)
    const int bm = blockIdx.x * 128;

    float acc[2][8][4];
#pragma unroll
    for (int mi = 0; mi < 2; ++mi)
#pragma unroll
        for (int nj = 0; nj < 8; ++nj)
#pragma unroll
            for (int r = 0; r < 4; ++r) acc[mi][nj][r] = 0.f;

    // ---- cp.async issue of one 32-deep k tile into stage s
    auto issue = [&](int s, int tile) {
        const int kb = tile * GBK;
        {   // A: 128 rows x 4 chunks = 512 = one per thread
            int row = tid >> 2, c = tid & 3;
            int grow = bm + row;
            int ok = (grow < NA) ? 16 : 0;
            size_t go = (size_t)grow * IN_DIM + kb + c * 8;
            uint32_t d = sb + row * ROWB + c * 16;
            cp16(d + AHOF(s), Ahg + go, ok);
            cp16(d + ALOF(s), Alg + go, ok);
        }
#pragma unroll
        for (int rep = 0; rep < 2; ++rep) {   // B: 256 rows x 4 chunks = 1024
            int idx = tid + rep * 512;
            int row = idx >> 2, c = idx & 3;
            size_t go = (size_t)row * IN_DIM + kb + c * 8;
            uint32_t d = sb + row * ROWB + c * 16;
            cp16(d + BHOF(s), Bhg + go, 16);
            cp16(d + BLOF(s), Blg + go, 16);
        }
        asm volatile("cp.async.commit_group;\n" ::);
    };

    issue(0, 0); issue(1, 1); issue(2, 2);

    // ldmatrix lane addressing (constant across tiles, varies by stage/ks)
    const int arow  = wm + (lane & 15);             // + mi*16
    const int akoff = (lane >> 4) << 4;             // 0 or 16 bytes
    const int brow  = wn + ((lane >> 4) << 3) + (lane & 7);   // + jp*16
    const int bkoff = ((lane >> 3) & 1) << 4;       // 0 or 16 bytes

    for (int i = 0; i < NTILE; ++i) {
        const int s = i % NSTAGE;
        if (i <= NTILE - 3)
            asm volatile("cp.async.wait_group 2;\n" ::);
        else if (i == NTILE - 2)
            asm volatile("cp.async.wait_group 1;\n" ::);
        else
            asm volatile("cp.async.wait_group 0;\n" ::);
        __syncthreads();

#pragma unroll
        for (int ks = 0; ks < 2; ++ks) {
            uint32_t ah[2][4], al[2][4];
#pragma unroll
            for (int mi = 0; mi < 2; ++mi) {
                uint32_t aaddr = sb + AHOF(s) + (arow + mi * 16) * ROWB
                               + ks * 32 + akoff;
                LDSM_X4(ah[mi][0], ah[mi][1], ah[mi][2], ah[mi][3], aaddr);
                LDSM_X4(al[mi][0], al[mi][1], al[mi][2], al[mi][3],
                        aaddr + A_BYTES);
            }
#pragma unroll
            for (int jp = 0; jp < 4; ++jp) {
                uint32_t baddr = sb + BHOF(s) + (brow + jp * 16) * ROWB
                               + ks * 32 + bkoff;
                uint32_t bh[4], bl[4];
                LDSM_X4(bh[0], bh[1], bh[2], bh[3], baddr);
                LDSM_X4(bl[0], bl[1], bl[2], bl[3], baddr + B_BYTES);
#pragma unroll
                for (int mi = 0; mi < 2; ++mi) {
                    MMA_BF16(acc[mi][2 * jp], al[mi][0], al[mi][1], al[mi][2],
                             al[mi][3], bh[0], bh[1]);
                    MMA_BF16(acc[mi][2 * jp], ah[mi][0], ah[mi][1], ah[mi][2],
                             ah[mi][3], bl[0], bl[1]);
                    MMA_BF16(acc[mi][2 * jp], ah[mi][0], ah[mi][1], ah[mi][2],
                             ah[mi][3], bh[0], bh[1]);
                    MMA_BF16(acc[mi][2 * jp + 1], al[mi][0], al[mi][1],
                             al[mi][2], al[mi][3], bh[2], bh[3]);
                    MMA_BF16(acc[mi][2 * jp + 1], ah[mi][0], ah[mi][1],
                             ah[mi][2], ah[mi][3], bl[2], bl[3]);
                    MMA_BF16(acc[mi][2 * jp + 1], ah[mi][0], ah[mi][1],
                             ah[mi][2], ah[mi][3], bh[2], bh[3]);
                }
            }
        }
        __syncthreads();
        if (i + NSTAGE < NTILE) issue(s, i + NSTAGE);
    }

    // ---- epilogue: direct float2 stores
#pragma unroll
    for (int mi = 0; mi < 2; ++mi) {
        int row0 = bm + wm + mi * 16 + g;
#pragma unroll
        for (int nj = 0; nj < 8; ++nj) {
            int col = wn + nj * 8 + tg * 2;
            if (row0 < NA)
                *(float2*)&C[(size_t)row0 * HD + col] =
                    make_float2(acc[mi][nj][0], acc[mi][nj][1]);
            if (row0 + 8 < NA)
                *(float2*)&C[(size_t)(row0 + 8) * HD + col] =
                    make_float2(acc[mi][nj][2], acc[mi][nj][3]);
        }
    }
}

// ---------------- s_src[n,h] = z[n,h,:] . a_src  (warp per node) ------------
__global__ void __launch_bounds__(256) k_ssrc(const float* __restrict__ W_attn) {
    int gw = (blockIdx.x * blockDim.x + threadIdx.x) >> 5;
    int lane = threadIdx.x & 31;
    if (gw >= NA) return;
    const float4* zp = (const float4*)(g_z + (size_t)gw * HD);
    float4 v0 = zp[lane];
    float4 v1 = zp[lane + 32];
    float4 a4 = *(const float4*)(W_attn + (lane & 7) * 4);
    float acc0 = v0.x * a4.x + v0.y * a4.y + v0.z * a4.z + v0.w * a4.w;
    float acc1 = v1.x * a4.x + v1.y * a4.y + v1.z * a4.z + v1.w * a4.w;
#pragma unroll
    for (int off = 1; off < 8; off <<= 1) {
        acc0 += __shfl_xor_sync(0xffffffffu, acc0, off);
        acc1 += __shfl_xor_sync(0xffffffffu, acc1, off);
    }
    if ((lane & 7) == 0) {
        g_ssrc[(size_t)gw * NH + (lane >> 3)] = acc0;
        g_ssrc[(size_t)gw * NH + 4 + (lane >> 3)] = acc1;
    }
}

// ---------------- edge scores ------------------------------------------------
__global__ void __launch_bounds__(256) k_eval(const float* __restrict__ srl,
                                              const int* __restrict__ src) {
    __shared__ float sv[NH][FEAT];
    int tid = threadIdx.x;
#pragma unroll
    for (int i = tid; i < NH * FEAT; i += 256)
        ((float*)sv)[i] = g_vfeat[i];
    __syncthreads();

    int warp = tid >> 5, lane = tid & 31;
    int grp = lane >> 3, sl = lane & 7;
    int e = blockIdx.x * 32 + warp * 4 + grp;
    if (e >= NE) return;

    const float4* row = (const float4*)(srl + (size_t)e * FEAT);
    float acc[NH];
#pragma unroll
    for (int h = 0; h < NH; ++h) acc[h] = 0.f;
#pragma unroll
    for (int i = 0; i < 4; ++i) {
        float4 v = row[i * 8 + sl];
        int fb = (i * 8 + sl) * 4;
#pragma unroll
        for (int h = 0; h < NH; ++h) {
            acc[h] += v.x * sv[h][fb + 0];
            acc[h] += v.y * sv[h][fb + 1];
            acc[h] += v.z * sv[h][fb + 2];
            acc[h] += v.w * sv[h][fb + 3];
        }
    }
    float ev = 0.f;
#pragma unroll
    for (int h = 0; h < NH; ++h) {
        float v = acc[h];
        v += __shfl_xor_sync(0xffffffffu, v, 1, 8);
        v += __shfl_xor_sync(0xffffffffu, v, 2, 8);
        v += __shfl_xor_sync(0xffffffffu, v, 4, 8);
        if (h == sl) ev = v;
    }
    int sid = src[e];
    float x = g_ssrc[(size_t)sid * NH + sl] + ev;
    g_eval[(size_t)e * NH + sl] = (x > 0.f) ? x : 0.01f * x;
}

// ---------------- counting sort of edges by dst ----------------------------
__global__ void k_hist(const int* __restrict__ dst) {
    int t = blockIdx.x * blockDim.x + threadIdx.x;
    if (t < NE) atomicAdd(&g_counts[dst[t]], 1);
}

__global__ void __launch_bounds__(1024) k_scan() {
    __shared__ int sh[1024];
    int t = threadIdx.x;
    int base = t * 10;
    int local[10];
    int s = 0;
#pragma unroll
    for (int i = 0; i < 10; ++i) {
        int idx = base + i;
        int c = (idx < NP) ? g_counts[idx] : 0;
        local[i] = s;
        s += c;
    }
    sh[t] = s;
    __syncthreads();
    for (int off = 1; off < 1024; off <<= 1) {
        int v = (t >= off) ? sh[t - off] : 0;
        __syncthreads();
        sh[t] += v;
        __syncthreads();
    }
    int excl = sh[t] - s;
#pragma unroll
    for (int i = 0; i < 10; ++i) {
        int idx = base + i;
        if (idx < NP) {
            int o = excl + local[i];
            g_offsets[idx] = o;
            g_cursor[idx] = o;
        }
    }
}

__global__ void k_scatter(const int* __restrict__ dst) {
    int t = blockIdx.x * blockDim.x + threadIdx.x;
    if (t < NE) {
        int p = atomicAdd(&g_cursor[dst[t]], 1);
        g_edge_sorted[p] = t;
    }
}

// ---------------- per-segment softmax + weighted gather of z ---------------
__global__ void __launch_bounds__(256) k_segment(const int* __restrict__ src,
                                                 float* __restrict__ out) {
    int p = blockIdx.x;
    int t = threadIdx.x;
    int h = t >> 5;
    int start = g_offsets[p];
    int cnt = g_counts[p];
    float* op = out + (size_t)p * HD + t;
    if (cnt == 0) { *op = 0.f; return; }

    float m = -3.0e38f;
    for (int i = 0; i < cnt; ++i) {
        int eid = g_edge_sorted[start + i];
        m = fmaxf(m, g_eval[(size_t)eid * NH + h]);
    }
    float denom = 0.f, acc = 0.f;
    for (int i = 0; i < cnt; ++i) {
        int eid = g_edge_sorted[start + i];
        float w = expf(g_eval[(size_t)eid * NH + h] - m);
        denom += w;
        int sid = src[eid];
        acc += w * g_z[(size_t)sid * HD + t];
    }
    *op = acc / denom;
}

// ---------------- launcher --------------------------------------------------
extern "C" void kernel_launch(void* const* d_in, const int* in_sizes, int n_in,
                              void* d_out, int out_size) {
    const float* h      = (const float*)d_in[0];
    const float* srl    = (const float*)d_in[1];
    const int*   src    = (const int*)d_in[2];
    const int*   dst    = (const int*)d_in[3];
    const float* W_fc   = (const float*)d_in[4];
    const float* W_feat = (const float*)d_in[5];
    const float* W_attn = (const float*)d_in[6];
    float* out = (float*)d_out;

    cudaFuncSetAttribute(k_gemm_ldsm,
                         cudaFuncAttributeMaxDynamicSharedMemorySize, GEMM_SMEM);

    k_zero_counts<<<(NP + 255) / 256, 256>>>();
    k_vfeat<<<(NH * FEAT + 255) / 256, 256>>>(W_feat, W_attn);

    __nv_bfloat16 *ahi, *alo, *bhi, *blo;
    float* zptr;
    cudaGetSymbolAddress((void**)&ahi, g_ahi);
    cudaGetSymbolAddress((void**)&alo, g_alo);
    cudaGetSymbolAddress((void**)&bhi, g_bhi);
    cudaGetSymbolAddress((void**)&blo, g_blo);
    cudaGetSymbolAddress((void**)&zptr, g_z);

    {
        int n4a = NA * IN_DIM / 4;
        k_split<<<(n4a + 255) / 256, 256>>>(h, ahi, alo, n4a);
        int n4b = HD * IN_DIM / 4;
        k_split<<<(n4b + 255) / 256, 256>>>(W_fc, bhi, blo, n4b);
    }

    {
        int grid = (NA + 127) / 128;   // 391
        k_gemm_ldsm<<<grid, 512, GEMM_SMEM>>>(ahi, alo, bhi, blo, zptr);
    }

    k_ssrc<<<(NA * 32 + 255) / 256, 256>>>(W_attn);
    k_eval<<<(NE + 31) / 32, 256>>>(srl, src);

    k_hist<<<(NE + 255) / 256, 256>>>(dst);
    k_scan<<<1, 1024>>>();
    k_scatter<<<(NE + 255) / 256, 256>>>(dst);

    k_segment<<<NP, 256>>>(src, out);
}

// round 10
// speedup vs baseline: 1.0971x; 1.0971x over previous
#include <cuda_runtime.h>
#include <cuda_bf16.h>
#include <cstdint>
#include <math.h>

// Problem constants (fixed by the dataset)
#define NA      50000
#define NP      10000
#define NE      400000
#define IN_DIM  512
#define FEAT    128
#define NH      8
#define OD      32
#define HD      256   // NH*OD

// ---------------- scratch (static device globals; no allocation) -----------
__device__ float g_z[(size_t)NA * HD];        // 51.2 MB
__device__ float g_ssrc[(size_t)NA * NH];
__device__ float g_eval[(size_t)NE * NH];     // sfeat then eval (in place)
__device__ float g_vfeat[NH * FEAT];
__device__ float g_uvec[NH * IN_DIM];         // u[h,k] = sum_d a_src[d] W_fc[h*32+d,k]
__device__ int   g_counts[NP];
__device__ int   g_offsets[NP];
__device__ int   g_cursor[NP];
__device__ int   g_edge_sorted[NE];

// ---------------- small utility kernels ------------------------------------
__global__ void k_zero_counts() {
    int t = blockIdx.x * blockDim.x + threadIdx.x;
    if (t < NP) g_counts[t] = 0;
}

__global__ void k_vfeat(const float* __restrict__ W_feat,
                        const float* __restrict__ W_attn) {
    int t = blockIdx.x * blockDim.x + threadIdx.x;
    if (t >= NH * FEAT) return;
    int h = t / FEAT, f = t % FEAT;
    float acc = 0.f;
#pragma unroll
    for (int d = 0; d < OD; ++d)
        acc += W_attn[2 * OD + d] * W_feat[(size_t)(h * OD + d) * FEAT + f];
    g_vfeat[t] = acc;
}

// u[h,k] = sum_d a_src[d] * W_fc[(h*OD+d)*IN_DIM + k]
__global__ void k_uvec(const float* __restrict__ W_fc,
                       const float* __restrict__ W_attn) {
    int t = blockIdx.x * blockDim.x + threadIdx.x;
    if (t >= NH * IN_DIM) return;
    int h8 = t >> 9, k = t & (IN_DIM - 1);
    float acc = 0.f;
#pragma unroll
    for (int d = 0; d < OD; ++d)
        acc += W_attn[d] * W_fc[(size_t)(h8 * OD + d) * IN_DIM + k];
    g_uvec[t] = acc;
}

// ---------------- s_src[n,h] = h[n,:] . u[h,:]  (warp per node) -------------
__global__ void __launch_bounds__(256) k_ssrc2(const float* __restrict__ hmat) {
    __shared__ float su[NH * IN_DIM];   // 16 KB
    int tid = threadIdx.x;
    for (int i = tid; i < NH * IN_DIM; i += 256) su[i] = g_uvec[i];
    __syncthreads();

    int gw = (blockIdx.x * 256 + tid) >> 5;
    int lane = tid & 31;
    if (gw >= NA) return;
    const float4* hr = (const float4*)(hmat + (size_t)gw * IN_DIM);
    float acc[NH];
#pragma unroll
    for (int h8 = 0; h8 < NH; ++h8) acc[h8] = 0.f;
#pragma unroll
    for (int j = 0; j < 4; ++j) {
        float4 hv = hr[j * 32 + lane];
        int c = (j * 32 + lane) * 4;
#pragma unroll
        for (int h8 = 0; h8 < NH; ++h8) {
            const float* up = su + h8 * IN_DIM + c;
            acc[h8] += hv.x * up[0] + hv.y * up[1] + hv.z * up[2] + hv.w * up[3];
        }
    }
#pragma unroll
    for (int off = 16; off >= 1; off >>= 1)
#pragma unroll
        for (int h8 = 0; h8 < NH; ++h8)
            acc[h8] += __shfl_xor_sync(0xffffffffu, acc[h8], off);
    if (lane == 0) {
#pragma unroll
        for (int h8 = 0; h8 < NH; ++h8)
            g_ssrc[(size_t)gw * NH + h8] = acc[h8];
    }
}

// ============ 3-term compensated bf16 tensor-core GEMM (R4 version) =========
#define GBM 128
#define GBN 128
#define GBK 16
#define KP  (GBK / 2)
#define SPAD 4
#define SSTR (KP + SPAD)
#define SIDX(buf, row, kp) ((((buf) * GBM) + (row)) * SSTR + (kp))
#define GEMM_SMEM_BYTES (4 * 2 * GBM * SSTR * 4)   // 49152

__device__ __forceinline__ void bf16_split2(float x, float y,
                                            uint32_t& hi, uint32_t& lo) {
    __nv_bfloat16 hx = __float2bfloat16_rn(x);
    __nv_bfloat16 hy = __float2bfloat16_rn(y);
    float rx = x - __bfloat162float(hx);
    float ry = y - __bfloat162float(hy);
    __nv_bfloat162 hp = __halves2bfloat162(hx, hy);
    __nv_bfloat162 lp = __floats2bfloat162_rn(rx, ry);
    hi = *reinterpret_cast<uint32_t*>(&hp);
    lo = *reinterpret_cast<uint32_t*>(&lp);
}

#define MMA_BF16(D, A0, A1, A2, A3, B0, B1)                                   \
    asm volatile(                                                             \
        "mma.sync.aligned.m16n8k16.row.col.f32.bf16.bf16.f32 "                \
        "{%0,%1,%2,%3}, {%4,%5,%6,%7}, {%8,%9}, {%0,%1,%2,%3};"               \
        : "+f"(D[0]), "+f"(D[1]), "+f"(D[2]), "+f"(D[3])                      \
        : "r"(A0), "r"(A1), "r"(A2), "r"(A3), "r"(B0), "r"(B1))

__global__ void __launch_bounds__(256, 2)
k_gemm_bf16x2(const float* __restrict__ A, const float* __restrict__ B,
              float* __restrict__ C) {
    const int M = NA, K = IN_DIM;
    extern __shared__ uint32_t sm[];
    uint32_t* Ah = sm;
    uint32_t* Al = sm + 2 * GBM * SSTR;
    uint32_t* Bh = sm + 4 * GBM * SSTR;
    uint32_t* Bl = sm + 6 * GBM * SSTR;

    const int bm = blockIdx.y * GBM;
    const int bn = blockIdx.x * GBN;
    const int tid = threadIdx.x;
    const int warp = tid >> 5, lane = tid & 31;
    const int g = lane >> 2, tg = lane & 3;
    const int wm = (warp >> 2) * 64;
    const int wn = (warp & 3) * 32;

    float acc[4][4][4];
#pragma unroll
    for (int mi = 0; mi < 4; ++mi)
#pragma unroll
        for (int nj = 0; nj < 4; ++nj)
#pragma unroll
            for (int r = 0; r < 4; ++r) acc[mi][nj][r] = 0.f;

    const int lr = tid >> 2;
    const int lc = (tid & 3) * 4;
    const int lkp = (tid & 3) * 2;
    const int NITER = K / GBK;

    float4 ra[2], rb[2];
#pragma unroll
    for (int it = 0; it < 2; ++it) {
        int row = lr + it * 64;
        int grow = bm + row;
        ra[it] = (grow < M) ? *(const float4*)(A + (size_t)grow * K + lc)
                            : make_float4(0.f, 0.f, 0.f, 0.f);
        rb[it] = *(const float4*)(B + (size_t)(bn + row) * K + lc);
    }
#pragma unroll
    for (int it = 0; it < 2; ++it) {
        int row = lr + it * 64;
        uint32_t h0, l0, h1, l1;
        bf16_split2(ra[it].x, ra[it].y, h0, l0);
        bf16_split2(ra[it].z, ra[it].w, h1, l1);
        Ah[SIDX(0, row, lkp)] = h0; Ah[SIDX(0, row, lkp + 1)] = h1;
        Al[SIDX(0, row, lkp)] = l0; Al[SIDX(0, row, lkp + 1)] = l1;
        bf16_split2(rb[it].x, rb[it].y, h0, l0);
        bf16_split2(rb[it].z, rb[it].w, h1, l1);
        Bh[SIDX(0, row, lkp)] = h0; Bh[SIDX(0, row, lkp + 1)] = h1;
        Bl[SIDX(0, row, lkp)] = l0; Bl[SIDX(0, row, lkp + 1)] = l1;
    }
    __syncthreads();

    for (int t = 0; t < NITER; ++t) {
        if (t + 1 < NITER) {
            int kb = (t + 1) * GBK;
#pragma unroll
            for (int it = 0; it < 2; ++it) {
                int row = lr + it * 64;
                int grow = bm + row;
                ra[it] = (grow < M)
                    ? *(const float4*)(A + (size_t)grow * K + kb + lc)
                    : make_float4(0.f, 0.f, 0.f, 0.f);
                rb[it] = *(const float4*)(B + (size_t)(bn + row) * K + kb + lc);
            }
        }

        const int buf = t & 1;
        uint32_t bhf[4][2], blf[4][2];
#pragma unroll
        for (int nj = 0; nj < 4; ++nj) {
            int row = wn + nj * 8 + g;
            bhf[nj][0] = Bh[SIDX(buf, row, tg)];
            bhf[nj][1] = Bh[SIDX(buf, row, tg + 4)];
            blf[nj][0] = Bl[SIDX(buf, row, tg)];
            blf[nj][1] = Bl[SIDX(buf, row, tg + 4)];
        }
#pragma unroll
        for (int mi = 0; mi < 4; ++mi) {
            int r0 = wm + mi * 16 + g;
            uint32_t ah0 = Ah[SIDX(buf, r0, tg)];
            uint32_t ah1 = Ah[SIDX(buf, r0 + 8, tg)];
            uint32_t ah2 = Ah[SIDX(buf, r0, tg + 4)];
            uint32_t ah3 = Ah[SIDX(buf, r0 + 8, tg + 4)];
            uint32_t al0 = Al[SIDX(buf, r0, tg)];
            uint32_t al1 = Al[SIDX(buf, r0 + 8, tg)];
            uint32_t al2 = Al[SIDX(buf, r0, tg + 4)];
            uint32_t al3 = Al[SIDX(buf, r0 + 8, tg + 4)];
#pragma unroll
            for (int nj = 0; nj < 4; ++nj) {
                MMA_BF16(acc[mi][nj], al0, al1, al2, al3, bhf[nj][0], bhf[nj][1]);
                MMA_BF16(acc[mi][nj], ah0, ah1, ah2, ah3, blf[nj][0], blf[nj][1]);
                MMA_BF16(acc[mi][nj], ah0, ah1, ah2, ah3, bhf[nj][0], bhf[nj][1]);
            }
        }

        if (t + 1 < NITER) {
            const int nb = (t + 1) & 1;
#pragma unroll
            for (int it = 0; it < 2; ++it) {
                int row = lr + it * 64;
                uint32_t h0, l0, h1, l1;
                bf16_split2(ra[it].x, ra[it].y, h0, l0);
                bf16_split2(ra[it].z, ra[it].w, h1, l1);
                Ah[SIDX(nb, row, lkp)] = h0; Ah[SIDX(nb, row, lkp + 1)] = h1;
                Al[SIDX(nb, row, lkp)] = l0; Al[SIDX(nb, row, lkp + 1)] = l1;
                bf16_split2(rb[it].x, rb[it].y, h0, l0);
                bf16_split2(rb[it].z, rb[it].w, h1, l1);
                Bh[SIDX(nb, row, lkp)] = h0; Bh[SIDX(nb, row, lkp + 1)] = h1;
                Bl[SIDX(nb, row, lkp)] = l0; Bl[SIDX(nb, row, lkp + 1)] = l1;
            }
            __syncthreads();
        }
    }

#pragma unroll
    for (int mi = 0; mi < 4; ++mi) {
        int row0 = bm + wm + mi * 16 + g;
#pragma unroll
        for (int nj = 0; nj < 4; ++nj) {
            int col = bn + wn + nj * 8 + tg * 2;
            if (row0 < M)
                *(float2*)&C[(size_t)row0 * HD + col] =
                    make_float2(acc[mi][nj][0], acc[mi][nj][1]);
            if (row0 + 8 < M)
                *(float2*)&C[(size_t)(row0 + 8) * HD + col] =
                    make_float2(acc[mi][nj][2], acc[mi][nj][3]);
        }
    }
}

// ---------------- edge features: sfeat[e,h] = srl_emb[e] . v[h] -------------
__global__ void __launch_bounds__(256) k_sfeat(const float* __restrict__ srl) {
    __shared__ float sv[NH][FEAT];
    int tid = threadIdx.x;
#pragma unroll
    for (int i = tid; i < NH * FEAT; i += 256)
        ((float*)sv)[i] = g_vfeat[i];
    __syncthreads();

    int warp = tid >> 5, lane = tid & 31;
    int grp = lane >> 3, sl = lane & 7;
    int e = blockIdx.x * 32 + warp * 4 + grp;
    if (e >= NE) return;

    const float4* row = (const float4*)(srl + (size_t)e * FEAT);
    float acc[NH];
#pragma unroll
    for (int h = 0; h < NH; ++h) acc[h] = 0.f;
#pragma unroll
    for (int i = 0; i < 4; ++i) {
        float4 v = row[i * 8 + sl];
        int fb = (i * 8 + sl) * 4;
#pragma unroll
        for (int h = 0; h < NH; ++h) {
            acc[h] += v.x * sv[h][fb + 0];
            acc[h] += v.y * sv[h][fb + 1];
            acc[h] += v.z * sv[h][fb + 2];
            acc[h] += v.w * sv[h][fb + 3];
        }
    }
    float ev = 0.f;
#pragma unroll
    for (int h = 0; h < NH; ++h) {
        float v = acc[h];
        v += __shfl_xor_sync(0xffffffffu, v, 1, 8);
        v += __shfl_xor_sync(0xffffffffu, v, 2, 8);
        v += __shfl_xor_sync(0xffffffffu, v, 4, 8);
        if (h == sl) ev = v;
    }
    g_eval[(size_t)e * NH + sl] = ev;     // raw sfeat; combine adds ssrc
}

// ---------------- eval = leaky_relu(ssrc[src] + sfeat) ----------------------
__global__ void __launch_bounds__(256) k_combine(const int* __restrict__ src) {
    int t = blockIdx.x * blockDim.x + threadIdx.x;
    if (t >= NE * NH) return;
    int e = t >> 3, sl = t & 7;
    int sid = __ldg(&src[e]);
    float x = g_ssrc[(size_t)sid * NH + sl] + g_eval[t];
    g_eval[t] = (x > 0.f) ? x : 0.01f * x;
}

// ---------------- counting sort of edges by dst ----------------------------
__global__ void k_hist(const int* __restrict__ dst) {
    int t = blockIdx.x * blockDim.x + threadIdx.x;
    if (t < NE) atomicAdd(&g_counts[dst[t]], 1);
}

__global__ void __launch_bounds__(1024) k_scan() {
    __shared__ int sh[1024];
    int t = threadIdx.x;
    int base = t * 10;
    int local[10];
    int s = 0;
#pragma unroll
    for (int i = 0; i < 10; ++i) {
        int idx = base + i;
        int c = (idx < NP) ? g_counts[idx] : 0;
        local[i] = s;
        s += c;
    }
    sh[t] = s;
    __syncthreads();
    for (int off = 1; off < 1024; off <<= 1) {
        int v = (t >= off) ? sh[t - off] : 0;
        __syncthreads();
        sh[t] += v;
        __syncthreads();
    }
    int excl = sh[t] - s;
#pragma unroll
    for (int i = 0; i < 10; ++i) {
        int idx = base + i;
        if (idx < NP) {
            int o = excl + local[i];
            g_offsets[idx] = o;
            g_cursor[idx] = o;
        }
    }
}

__global__ void k_scatter(const int* __restrict__ dst) {
    int t = blockIdx.x * blockDim.x + threadIdx.x;
    if (t < NE) {
        int p = atomicAdd(&g_cursor[dst[t]], 1);
        g_edge_sorted[p] = t;
    }
}

// -------- per-segment ONLINE softmax + weighted gather (one pass) ----------
__global__ void __launch_bounds__(256) k_segment(const int* __restrict__ src,
                                                 float* __restrict__ out) {
    int p = blockIdx.x;
    int t = threadIdx.x;
    int h = t >> 5;
    int start = g_offsets[p];
    int cnt = g_counts[p];
    float* op = out + (size_t)p * HD + t;
    if (cnt == 0) { *op = 0.f; return; }

    float m = -3.0e38f, denom = 0.f, acc = 0.f;
    for (int i = 0; i < cnt; ++i) {
        int eid = g_edge_sorted[start + i];
        float e = g_eval[(size_t)eid * NH + h];
        float mn = fmaxf(m, e);
        float scale = __expf(m - mn);          // 0 on first iter, 1 if no change
        float w = __expf(e - mn);
        int sid = __ldg(&src[eid]);
        denom = denom * scale + w;
        acc = acc * scale + w * g_z[(size_t)sid * HD + t];
        m = mn;
    }
    *op = acc / denom;
}

// ---------------- launcher --------------------------------------------------
extern "C" void kernel_launch(void* const* d_in, const int* in_sizes, int n_in,
                              void* d_out, int out_size) {
    const float* h      = (const float*)d_in[0];
    const float* srl    = (const float*)d_in[1];
    const int*   src    = (const int*)d_in[2];
    const int*   dst    = (const int*)d_in[3];
    const float* W_fc   = (const float*)d_in[4];
    const float* W_feat = (const float*)d_in[5];
    const float* W_attn = (const float*)d_in[6];
    float* out = (float*)d_out;

    // streams/events created once, on the first (non-captured) call; the
    // captured work is identical every call.
    static cudaStream_t s1 = nullptr, s2 = nullptr;
    static cudaEvent_t ef = nullptr, ej1 = nullptr, ej2 = nullptr;
    if (s1 == nullptr) {
        cudaStreamCreateWithFlags(&s1, cudaStreamNonBlocking);
        cudaStreamCreateWithFlags(&s2, cudaStreamNonBlocking);
        cudaEventCreateWithFlags(&ef,  cudaEventDisableTiming);
        cudaEventCreateWithFlags(&ej1, cudaEventDisableTiming);
        cudaEventCreateWithFlags(&ej2, cudaEventDisableTiming);
    }

    float* zptr;
    cudaGetSymbolAddress((void**)&zptr, g_z);

    // fork side streams off the main (capture-origin) stream
    cudaEventRecord(ef, 0);
    cudaStreamWaitEvent(s1, ef, 0);
    cudaStreamWaitEvent(s2, ef, 0);

    // side chain 1: edge counting sort (independent of GEMM)
    k_zero_counts<<<(NP + 255) / 256, 256, 0, s1>>>();
    k_hist<<<(NE + 255) / 256, 256, 0, s1>>>(dst);
    k_scan<<<1, 1024, 0, s1>>>();
    k_scatter<<<(NE + 255) / 256, 256, 0, s1>>>(dst);
    cudaEventRecord(ej1, s1);

    // side chain 2: attention logits (independent of GEMM via u-vector trick)
    k_uvec<<<(NH * IN_DIM + 255) / 256, 256, 0, s2>>>(W_fc, W_attn);
    k_vfeat<<<(NH * FEAT + 255) / 256, 256, 0, s2>>>(W_feat, W_attn);
    k_ssrc2<<<(NA * 32 + 255) / 256, 256, 0, s2>>>(h);
    k_sfeat<<<(NE + 31) / 32, 256, 0, s2>>>(srl);
    k_combine<<<(NE * NH + 255) / 256, 256, 0, s2>>>(src);
    cudaEventRecord(ej2, s2);

    // main: the tensor-core GEMM (critical path)
    {
        dim3 grid(HD / GBN, (NA + GBM - 1) / GBM);
        k_gemm_bf16x2<<<grid, 256, GEMM_SMEM_BYTES>>>(h, W_fc, zptr);
    }

    // join, then the only kernel that needs everything
    cudaStreamWaitEvent(0, ej1, 0);
    cudaStreamWaitEvent(0, ej2, 0);
    k_segment<<<NP, 256>>>(src, out);
}

// round 11
// speedup vs baseline: 1.2248x; 1.1164x over previous
#include <cuda_runtime.h>
#include <cuda_bf16.h>
#include <cstdint>
#include <math.h>

// Problem constants (fixed by the dataset)
#define NA      50000
#define NP      10000
#define NE      400000
#define IN_DIM  512
#define FEAT    128
#define NH      8
#define OD      32
#define HD      256   // NH*OD

// ---------------- scratch (static device globals; no allocation) -----------
__device__ float g_z[(size_t)NA * HD];        // 51.2 MB
__device__ float g_ssrc[(size_t)NA * NH];
__device__ float g_eval[(size_t)NE * NH];     // sfeat then eval (in place)
__device__ float g_alpha[(size_t)NE * NH];    // softmax weights, SORTED layout
__device__ float g_vfeat[NH * FEAT];
__device__ float g_uvec[NH * IN_DIM];
__device__ int   g_counts[NP];
__device__ int   g_offsets[NP];
__device__ int   g_cursor[NP];
__device__ int   g_edge_sorted[NE];
__device__ int   g_src_sorted[NE];

// ---------------- small utility kernels ------------------------------------
__global__ void k_zero_counts() {
    int t = blockIdx.x * blockDim.x + threadIdx.x;
    if (t < NP) g_counts[t] = 0;
}

__global__ void k_vfeat(const float* __restrict__ W_feat,
                        const float* __restrict__ W_attn) {
    int t = blockIdx.x * blockDim.x + threadIdx.x;
    if (t >= NH * FEAT) return;
    int h = t / FEAT, f = t % FEAT;
    float acc = 0.f;
#pragma unroll
    for (int d = 0; d < OD; ++d)
        acc += W_attn[2 * OD + d] * W_feat[(size_t)(h * OD + d) * FEAT + f];
    g_vfeat[t] = acc;
}

__global__ void k_uvec(const float* __restrict__ W_fc,
                       const float* __restrict__ W_attn) {
    int t = blockIdx.x * blockDim.x + threadIdx.x;
    if (t >= NH * IN_DIM) return;
    int h8 = t >> 9, k = t & (IN_DIM - 1);
    float acc = 0.f;
#pragma unroll
    for (int d = 0; d < OD; ++d)
        acc += W_attn[d] * W_fc[(size_t)(h8 * OD + d) * IN_DIM + k];
    g_uvec[t] = acc;
}

// ---------------- s_src[n,h] = h[n,:] . u[h,:]  (warp per node) -------------
__global__ void __launch_bounds__(256) k_ssrc2(const float* __restrict__ hmat) {
    __shared__ float su[NH * IN_DIM];   // 16 KB
    int tid = threadIdx.x;
    for (int i = tid; i < NH * IN_DIM; i += 256) su[i] = g_uvec[i];
    __syncthreads();

    int gw = (blockIdx.x * 256 + tid) >> 5;
    int lane = tid & 31;
    if (gw >= NA) return;
    const float4* hr = (const float4*)(hmat + (size_t)gw * IN_DIM);
    float acc[NH];
#pragma unroll
    for (int h8 = 0; h8 < NH; ++h8) acc[h8] = 0.f;
#pragma unroll
    for (int j = 0; j < 4; ++j) {
        float4 hv = hr[j * 32 + lane];
        int c = (j * 32 + lane) * 4;
#pragma unroll
        for (int h8 = 0; h8 < NH; ++h8) {
            const float* up = su + h8 * IN_DIM + c;
            acc[h8] += hv.x * up[0] + hv.y * up[1] + hv.z * up[2] + hv.w * up[3];
        }
    }
#pragma unroll
    for (int off = 16; off >= 1; off >>= 1)
#pragma unroll
        for (int h8 = 0; h8 < NH; ++h8)
            acc[h8] += __shfl_xor_sync(0xffffffffu, acc[h8], off);
    if (lane == 0) {
#pragma unroll
        for (int h8 = 0; h8 < NH; ++h8)
            g_ssrc[(size_t)gw * NH + h8] = acc[h8];
    }
}

// ============ 3-term compensated bf16 tensor-core GEMM (N-half) =============
#define GBM 128
#define GBN 128
#define GBK 16
#define KP  (GBK / 2)
#define SPAD 4
#define SSTR (KP + SPAD)
#define SIDX(buf, row, kp) ((((buf) * GBM) + (row)) * SSTR + (kp))
#define GEMM_SMEM_BYTES (4 * 2 * GBM * SSTR * 4)   // 49152

__device__ __forceinline__ void bf16_split2(float x, float y,
                                            uint32_t& hi, uint32_t& lo) {
    __nv_bfloat16 hx = __float2bfloat16_rn(x);
    __nv_bfloat16 hy = __float2bfloat16_rn(y);
    float rx = x - __bfloat162float(hx);
    float ry = y - __bfloat162float(hy);
    __nv_bfloat162 hp = __halves2bfloat162(hx, hy);
    __nv_bfloat162 lp = __floats2bfloat162_rn(rx, ry);
    hi = *reinterpret_cast<uint32_t*>(&hp);
    lo = *reinterpret_cast<uint32_t*>(&lp);
}

#define MMA_BF16(D, A0, A1, A2, A3, B0, B1)                                   \
    asm volatile(                                                             \
        "mma.sync.aligned.m16n8k16.row.col.f32.bf16.bf16.f32 "                \
        "{%0,%1,%2,%3}, {%4,%5,%6,%7}, {%8,%9}, {%0,%1,%2,%3};"               \
        : "+f"(D[0]), "+f"(D[1]), "+f"(D[2]), "+f"(D[3])                      \
        : "r"(A0), "r"(A1), "r"(A2), "r"(A3), "r"(B0), "r"(B1))

__global__ void __launch_bounds__(256, 2)
k_gemm_bf16x2(const float* __restrict__ A, const float* __restrict__ B,
              float* __restrict__ C, int bn) {
    const int M = NA, K = IN_DIM;
    extern __shared__ uint32_t sm[];
    uint32_t* Ah = sm;
    uint32_t* Al = sm + 2 * GBM * SSTR;
    uint32_t* Bh = sm + 4 * GBM * SSTR;
    uint32_t* Bl = sm + 6 * GBM * SSTR;

    const int bm = blockIdx.x * GBM;
    const int tid = threadIdx.x;
    const int warp = tid >> 5, lane = tid & 31;
    const int g = lane >> 2, tg = lane & 3;
    const int wm = (warp >> 2) * 64;
    const int wn = (warp & 3) * 32;

    float acc[4][4][4];
#pragma unroll
    for (int mi = 0; mi < 4; ++mi)
#pragma unroll
        for (int nj = 0; nj < 4; ++nj)
#pragma unroll
            for (int r = 0; r < 4; ++r) acc[mi][nj][r] = 0.f;

    const int lr = tid >> 2;
    const int lc = (tid & 3) * 4;
    const int lkp = (tid & 3) * 2;
    const int NITER = K / GBK;

    float4 ra[2], rb[2];
#pragma unroll
    for (int it = 0; it < 2; ++it) {
        int row = lr + it * 64;
        int grow = bm + row;
        ra[it] = (grow < M) ? *(const float4*)(A + (size_t)grow * K + lc)
                            : make_float4(0.f, 0.f, 0.f, 0.f);
        rb[it] = *(const float4*)(B + (size_t)(bn + row) * K + lc);
    }
#pragma unroll
    for (int it = 0; it < 2; ++it) {
        int row = lr + it * 64;
        uint32_t h0, l0, h1, l1;
        bf16_split2(ra[it].x, ra[it].y, h0, l0);
        bf16_split2(ra[it].z, ra[it].w, h1, l1);
        Ah[SIDX(0, row, lkp)] = h0; Ah[SIDX(0, row, lkp + 1)] = h1;
        Al[SIDX(0, row, lkp)] = l0; Al[SIDX(0, row, lkp + 1)] = l1;
        bf16_split2(rb[it].x, rb[it].y, h0, l0);
        bf16_split2(rb[it].z, rb[it].w, h1, l1);
        Bh[SIDX(0, row, lkp)] = h0; Bh[SIDX(0, row, lkp + 1)] = h1;
        Bl[SIDX(0, row, lkp)] = l0; Bl[SIDX(0, row, lkp + 1)] = l1;
    }
    __syncthreads();

    for (int t = 0; t < NITER; ++t) {
        if (t + 1 < NITER) {
            int kb = (t + 1) * GBK;
#pragma unroll
            for (int it = 0; it < 2; ++it) {
                int row = lr + it * 64;
                int grow = bm + row;
                ra[it] = (grow < M)
                    ? *(const float4*)(A + (size_t)grow * K + kb + lc)
                    : make_float4(0.f, 0.f, 0.f, 0.f);
                rb[it] = *(const float4*)(B + (size_t)(bn + row) * K + kb + lc);
            }
        }

        const int buf = t & 1;
        uint32_t bhf[4][2], blf[4][2];
#pragma unroll
        for (int nj = 0; nj < 4; ++nj) {
            int row = wn + nj * 8 + g;
            bhf[nj][0] = Bh[SIDX(buf, row, tg)];
            bhf[nj][1] = Bh[SIDX(buf, row, tg + 4)];
            blf[nj][0] = Bl[SIDX(buf, row, tg)];
            blf[nj][1] = Bl[SIDX(buf, row, tg + 4)];
        }
#pragma unroll
        for (int mi = 0; mi < 4; ++mi) {
            int r0 = wm + mi * 16 + g;
            uint32_t ah0 = Ah[SIDX(buf, r0, tg)];
            uint32_t ah1 = Ah[SIDX(buf, r0 + 8, tg)];
            uint32_t ah2 = Ah[SIDX(buf, r0, tg + 4)];
            uint32_t ah3 = Ah[SIDX(buf, r0 + 8, tg + 4)];
            uint32_t al0 = Al[SIDX(buf, r0, tg)];
            uint32_t al1 = Al[SIDX(buf, r0 + 8, tg)];
            uint32_t al2 = Al[SIDX(buf, r0, tg + 4)];
            uint32_t al3 = Al[SIDX(buf, r0 + 8, tg + 4)];
#pragma unroll
            for (int nj = 0; nj < 4; ++nj) {
                MMA_BF16(acc[mi][nj], al0, al1, al2, al3, bhf[nj][0], bhf[nj][1]);
                MMA_BF16(acc[mi][nj], ah0, ah1, ah2, ah3, blf[nj][0], blf[nj][1]);
                MMA_BF16(acc[mi][nj], ah0, ah1, ah2, ah3, bhf[nj][0], bhf[nj][1]);
            }
        }

        if (t + 1 < NITER) {
            const int nb = (t + 1) & 1;
#pragma unroll
            for (int it = 0; it < 2; ++it) {
                int row = lr + it * 64;
                uint32_t h0, l0, h1, l1;
                bf16_split2(ra[it].x, ra[it].y, h0, l0);
                bf16_split2(ra[it].z, ra[it].w, h1, l1);
                Ah[SIDX(nb, row, lkp)] = h0; Ah[SIDX(nb, row, lkp + 1)] = h1;
                Al[SIDX(nb, row, lkp)] = l0; Al[SIDX(nb, row, lkp + 1)] = l1;
                bf16_split2(rb[it].x, rb[it].y, h0, l0);
                bf16_split2(rb[it].z, rb[it].w, h1, l1);
                Bh[SIDX(nb, row, lkp)] = h0; Bh[SIDX(nb, row, lkp + 1)] = h1;
                Bl[SIDX(nb, row, lkp)] = l0; Bl[SIDX(nb, row, lkp + 1)] = l1;
            }
            __syncthreads();
        }
    }

#pragma unroll
    for (int mi = 0; mi < 4; ++mi) {
        int row0 = bm + wm + mi * 16 + g;
#pragma unroll
        for (int nj = 0; nj < 4; ++nj) {
            int col = bn + wn + nj * 8 + tg * 2;
            if (row0 < M)
                *(float2*)&C[(size_t)row0 * HD + col] =
                    make_float2(acc[mi][nj][0], acc[mi][nj][1]);
            if (row0 + 8 < M)
                *(float2*)&C[(size_t)(row0 + 8) * HD + col] =
                    make_float2(acc[mi][nj][2], acc[mi][nj][3]);
        }
    }
}

// ---------------- edge features: sfeat[e,h] = srl_emb[e] . v[h] -------------
__global__ void __launch_bounds__(256) k_sfeat(const float* __restrict__ srl) {
    __shared__ float sv[NH][FEAT];
    int tid = threadIdx.x;
#pragma unroll
    for (int i = tid; i < NH * FEAT; i += 256)
        ((float*)sv)[i] = g_vfeat[i];
    __syncthreads();

    int warp = tid >> 5, lane = tid & 31;
    int grp = lane >> 3, sl = lane & 7;
    int e = blockIdx.x * 32 + warp * 4 + grp;
    if (e >= NE) return;

    const float4* row = (const float4*)(srl + (size_t)e * FEAT);
    float acc[NH];
#pragma unroll
    for (int h = 0; h < NH; ++h) acc[h] = 0.f;
#pragma unroll
    for (int i = 0; i < 4; ++i) {
        float4 v = row[i * 8 + sl];
        int fb = (i * 8 + sl) * 4;
#pragma unroll
        for (int h = 0; h < NH; ++h) {
            acc[h] += v.x * sv[h][fb + 0];
            acc[h] += v.y * sv[h][fb + 1];
            acc[h] += v.z * sv[h][fb + 2];
            acc[h] += v.w * sv[h][fb + 3];
        }
    }
    float ev = 0.f;
#pragma unroll
    for (int h = 0; h < NH; ++h) {
        float v = acc[h];
        v += __shfl_xor_sync(0xffffffffu, v, 1, 8);
        v += __shfl_xor_sync(0xffffffffu, v, 2, 8);
        v += __shfl_xor_sync(0xffffffffu, v, 4, 8);
        if (h == sl) ev = v;
    }
    g_eval[(size_t)e * NH + sl] = ev;
}

// ---------------- eval = leaky_relu(ssrc[src] + sfeat) ----------------------
__global__ void __launch_bounds__(256) k_combine(const int* __restrict__ src) {
    int t = blockIdx.x * blockDim.x + threadIdx.x;
    if (t >= NE * NH) return;
    int e = t >> 3, sl = t & 7;
    int sid = __ldg(&src[e]);
    float x = g_ssrc[(size_t)sid * NH + sl] + g_eval[t];
    g_eval[t] = (x > 0.f) ? x : 0.01f * x;
}

// ---------------- counting sort of edges by dst ----------------------------
__global__ void k_hist(const int* __restrict__ dst) {
    int t = blockIdx.x * blockDim.x + threadIdx.x;
    if (t < NE) atomicAdd(&g_counts[dst[t]], 1);
}

__global__ void __launch_bounds__(1024) k_scan() {
    __shared__ int sh[1024];
    int t = threadIdx.x;
    int base = t * 10;
    int local[10];
    int s = 0;
#pragma unroll
    for (int i = 0; i < 10; ++i) {
        int idx = base + i;
        int c = (idx < NP) ? g_counts[idx] : 0;
        local[i] = s;
        s += c;
    }
    sh[t] = s;
    __syncthreads();
    for (int off = 1; off < 1024; off <<= 1) {
        int v = (t >= off) ? sh[t - off] : 0;
        __syncthreads();
        sh[t] += v;
        __syncthreads();
    }
    int excl = sh[t] - s;
#pragma unroll
    for (int i = 0; i < 10; ++i) {
        int idx = base + i;
        if (idx < NP) {
            int o = excl + local[i];
            g_offsets[idx] = o;
            g_cursor[idx] = o;
        }
    }
}

__global__ void k_scatter(const int* __restrict__ dst,
                          const int* __restrict__ src) {
    int t = blockIdx.x * blockDim.x + threadIdx.x;
    if (t < NE) {
        int p = atomicAdd(&g_cursor[dst[t]], 1);
        g_edge_sorted[p] = t;
        g_src_sorted[p] = src[t];
    }
}

// -------- softmax weights per segment (off critical path) ------------------
// block = segment p; warp h handles head h, 32 lanes parallel over edges
__global__ void __launch_bounds__(256) k_alpha() {
    int p = blockIdx.x;
    int t = threadIdx.x;
    int h = t >> 5, lane = t & 31;
    int start = g_offsets[p];
    int cnt = g_counts[p];
    if (cnt == 0) return;

    float m = -3.0e38f;
    for (int i = lane; i < cnt; i += 32) {
        int eid = g_edge_sorted[start + i];
        m = fmaxf(m, g_eval[(size_t)eid * NH + h]);
    }
#pragma unroll
    for (int off = 16; off >= 1; off >>= 1)
        m = fmaxf(m, __shfl_xor_sync(0xffffffffu, m, off));

    float s = 0.f;
    for (int i = lane; i < cnt; i += 32) {
        int eid = g_edge_sorted[start + i];
        s += __expf(g_eval[(size_t)eid * NH + h] - m);
    }
#pragma unroll
    for (int off = 16; off >= 1; off >>= 1)
        s += __shfl_xor_sync(0xffffffffu, s, off);
    float inv = 1.f / s;

    for (int i = lane; i < cnt; i += 32) {
        int pos = start + i;
        int eid = g_edge_sorted[pos];
        g_alpha[(size_t)pos * NH + h] =
            __expf(g_eval[(size_t)eid * NH + h] - m) * inv;
    }
}

// -------- pure weighted gather over 128 output channels --------------------
__global__ void __launch_bounds__(128) k_gather(float* __restrict__ out,
                                                int colbase) {
    int p = blockIdx.x;
    int t = threadIdx.x;
    int ch = colbase + t;
    int start = g_offsets[p];
    int cnt = g_counts[p];
    int hh = ch >> 5;
    float acc = 0.f;
#pragma unroll 4
    for (int i = 0; i < cnt; ++i) {
        int pos = start + i;
        float a = __ldg(&g_alpha[(size_t)pos * NH + hh]);
        int sid = __ldg(&g_src_sorted[pos]);
        acc += a * __ldg(&g_z[(size_t)sid * HD + ch]);
    }
    out[(size_t)p * HD + ch] = acc;
}

// ---------------- launcher --------------------------------------------------
extern "C" void kernel_launch(void* const* d_in, const int* in_sizes, int n_in,
                              void* d_out, int out_size) {
    const float* h      = (const float*)d_in[0];
    const float* srl    = (const float*)d_in[1];
    const int*   src    = (const int*)d_in[2];
    const int*   dst    = (const int*)d_in[3];
    const float* W_fc   = (const float*)d_in[4];
    const float* W_feat = (const float*)d_in[5];
    const float* W_attn = (const float*)d_in[6];
    float* out = (float*)d_out;

    static cudaStream_t s1 = nullptr, s2 = nullptr;
    static cudaEvent_t ef = nullptr, ej2 = nullptr, ejA = nullptr,
                       eg0 = nullptr, ejg = nullptr;
    if (s1 == nullptr) {
        cudaStreamCreateWithFlags(&s1, cudaStreamNonBlocking);
        cudaStreamCreateWithFlags(&s2, cudaStreamNonBlocking);
        cudaEventCreateWithFlags(&ef,  cudaEventDisableTiming);
        cudaEventCreateWithFlags(&ej2, cudaEventDisableTiming);
        cudaEventCreateWithFlags(&ejA, cudaEventDisableTiming);
        cudaEventCreateWithFlags(&eg0, cudaEventDisableTiming);
        cudaEventCreateWithFlags(&ejg, cudaEventDisableTiming);
    }

    float* zptr;
    cudaGetSymbolAddress((void**)&zptr, g_z);

    // fork
    cudaEventRecord(ef, 0);
    cudaStreamWaitEvent(s1, ef, 0);
    cudaStreamWaitEvent(s2, ef, 0);

    // side chain 2: attention logits (independent of GEMM)
    k_uvec<<<(NH * IN_DIM + 255) / 256, 256, 0, s2>>>(W_fc, W_attn);
    k_vfeat<<<(NH * FEAT + 255) / 256, 256, 0, s2>>>(W_feat, W_attn);
    k_ssrc2<<<(NA * 32 + 255) / 256, 256, 0, s2>>>(h);
    k_sfeat<<<(NE + 31) / 32, 256, 0, s2>>>(srl);
    k_combine<<<(NE * NH + 255) / 256, 256, 0, s2>>>(src);
    cudaEventRecord(ej2, s2);

    // side chain 1: counting sort, then alpha (needs logits too)
    k_zero_counts<<<(NP + 255) / 256, 256, 0, s1>>>();
    k_hist<<<(NE + 255) / 256, 256, 0, s1>>>(dst);
    k_scan<<<1, 1024, 0, s1>>>();
    k_scatter<<<(NE + 255) / 256, 256, 0, s1>>>(dst, src);
    cudaStreamWaitEvent(s1, ej2, 0);
    k_alpha<<<NP, 256, 0, s1>>>();
    cudaEventRecord(ejA, s1);

    // main stream: GEMM halves (critical path)
    {
        int grid = (NA + GBM - 1) / GBM;   // 391
        k_gemm_bf16x2<<<grid, 256, GEMM_SMEM_BYTES>>>(h, W_fc, zptr, 0);
        cudaEventRecord(eg0, 0);
        k_gemm_bf16x2<<<grid, 256, GEMM_SMEM_BYTES>>>(h, W_fc, zptr, 128);
    }

    // gather cols 0-127 overlaps GEMM half 2 (on s2)
    cudaStreamWaitEvent(s2, eg0, 0);
    cudaStreamWaitEvent(s2, ejA, 0);
    k_gather<<<NP, 128, 0, s2>>>(out, 0);
    cudaEventRecord(ejg, s2);

    // gather cols 128-255 after GEMM half 2, then join
    cudaStreamWaitEvent(0, ejA, 0);
    k_gather<<<NP, 128>>>(out, 128);
    cudaStreamWaitEvent(0, ejg, 0);
}

// round 12
// speedup vs baseline: 1.2478x; 1.0188x over previous
#include <cuda_runtime.h>
#include <cuda_bf16.h>
#include <cstdint>
#include <math.h>

// Problem constants (fixed by the dataset)
#define NA      50000
#define NP      10000
#define NE      400000
#define IN_DIM  512
#define FEAT    128
#define NH      8
#define OD      32
#define HD      256   // NH*OD

// ---------------- scratch (static device globals; no allocation) -----------
__device__ float g_z[(size_t)NA * HD];        // 51.2 MB
__device__ float g_ssrc[(size_t)NA * NH];
__device__ float g_eval[(size_t)NE * NH];     // final leaky-relu logits
__device__ float g_alpha[(size_t)NE * NH];    // softmax weights, SORTED layout
__device__ float g_vfeat[NH * FEAT];
__device__ float g_uvec[NH * IN_DIM];
__device__ int   g_counts[NP];
__device__ int   g_offsets[NP];
__device__ int   g_cursor[NP];
__device__ int   g_edge_sorted[NE];
__device__ int   g_src_sorted[NE];

// ---------------- small utility kernels ------------------------------------
__global__ void k_zero_counts() {
    int t = blockIdx.x * blockDim.x + threadIdx.x;
    if (t < NP) g_counts[t] = 0;
}

__global__ void k_vfeat(const float* __restrict__ W_feat,
                        const float* __restrict__ W_attn) {
    int t = blockIdx.x * blockDim.x + threadIdx.x;
    if (t >= NH * FEAT) return;
    int h = t / FEAT, f = t % FEAT;
    float acc = 0.f;
#pragma unroll
    for (int d = 0; d < OD; ++d)
        acc += W_attn[2 * OD + d] * W_feat[(size_t)(h * OD + d) * FEAT + f];
    g_vfeat[t] = acc;
}

__global__ void k_uvec(const float* __restrict__ W_fc,
                       const float* __restrict__ W_attn) {
    int t = blockIdx.x * blockDim.x + threadIdx.x;
    if (t >= NH * IN_DIM) return;
    int h8 = t >> 9, k = t & (IN_DIM - 1);
    float acc = 0.f;
#pragma unroll
    for (int d = 0; d < OD; ++d)
        acc += W_attn[d] * W_fc[(size_t)(h8 * OD + d) * IN_DIM + k];
    g_uvec[t] = acc;
}

// ---------------- s_src[n,h] = h[n,:] . u[h,:]  (warp per node) -------------
__global__ void __launch_bounds__(256) k_ssrc2(const float* __restrict__ hmat) {
    __shared__ float su[NH * IN_DIM];   // 16 KB
    int tid = threadIdx.x;
    for (int i = tid; i < NH * IN_DIM; i += 256) su[i] = g_uvec[i];
    __syncthreads();

    int gw = (blockIdx.x * 256 + tid) >> 5;
    int lane = tid & 31;
    if (gw >= NA) return;
    const float4* hr = (const float4*)(hmat + (size_t)gw * IN_DIM);
    float acc[NH];
#pragma unroll
    for (int h8 = 0; h8 < NH; ++h8) acc[h8] = 0.f;
#pragma unroll
    for (int j = 0; j < 4; ++j) {
        float4 hv = hr[j * 32 + lane];
        int c = (j * 32 + lane) * 4;
#pragma unroll
        for (int h8 = 0; h8 < NH; ++h8) {
            const float* up = su + h8 * IN_DIM + c;
            acc[h8] += hv.x * up[0] + hv.y * up[1] + hv.z * up[2] + hv.w * up[3];
        }
    }
#pragma unroll
    for (int off = 16; off >= 1; off >>= 1)
#pragma unroll
        for (int h8 = 0; h8 < NH; ++h8)
            acc[h8] += __shfl_xor_sync(0xffffffffu, acc[h8], off);
    if (lane == 0) {
#pragma unroll
        for (int h8 = 0; h8 < NH; ++h8)
            g_ssrc[(size_t)gw * NH + h8] = acc[h8];
    }
}

// ============ 3-term compensated bf16 tensor-core GEMM (N-half) =============
#define GBM 128
#define GBN 128
#define GBK 16
#define KP  (GBK / 2)
#define SPAD 4
#define SSTR (KP + SPAD)
#define SIDX(buf, row, kp) ((((buf) * GBM) + (row)) * SSTR + (kp))
#define GEMM_SMEM_BYTES (4 * 2 * GBM * SSTR * 4)   // 49152

__device__ __forceinline__ void bf16_split2(float x, float y,
                                            uint32_t& hi, uint32_t& lo) {
    __nv_bfloat16 hx = __float2bfloat16_rn(x);
    __nv_bfloat16 hy = __float2bfloat16_rn(y);
    float rx = x - __bfloat162float(hx);
    float ry = y - __bfloat162float(hy);
    __nv_bfloat162 hp = __halves2bfloat162(hx, hy);
    __nv_bfloat162 lp = __floats2bfloat162_rn(rx, ry);
    hi = *reinterpret_cast<uint32_t*>(&hp);
    lo = *reinterpret_cast<uint32_t*>(&lp);
}

#define MMA_BF16(D, A0, A1, A2, A3, B0, B1)                                   \
    asm volatile(                                                             \
        "mma.sync.aligned.m16n8k16.row.col.f32.bf16.bf16.f32 "                \
        "{%0,%1,%2,%3}, {%4,%5,%6,%7}, {%8,%9}, {%0,%1,%2,%3};"               \
        : "+f"(D[0]), "+f"(D[1]), "+f"(D[2]), "+f"(D[3])                      \
        : "r"(A0), "r"(A1), "r"(A2), "r"(A3), "r"(B0), "r"(B1))

__global__ void __launch_bounds__(256, 2)
k_gemm_bf16x2(const float* __restrict__ A, const float* __restrict__ B,
              float* __restrict__ C, int bn) {
    const int M = NA, K = IN_DIM;
    extern __shared__ uint32_t sm[];
    uint32_t* Ah = sm;
    uint32_t* Al = sm + 2 * GBM * SSTR;
    uint32_t* Bh = sm + 4 * GBM * SSTR;
    uint32_t* Bl = sm + 6 * GBM * SSTR;

    const int bm = blockIdx.x * GBM;
    const int tid = threadIdx.x;
    const int warp = tid >> 5, lane = tid & 31;
    const int g = lane >> 2, tg = lane & 3;
    const int wm = (warp >> 2) * 64;
    const int wn = (warp & 3) * 32;

    float acc[4][4][4];
#pragma unroll
    for (int mi = 0; mi < 4; ++mi)
#pragma unroll
        for (int nj = 0; nj < 4; ++nj)
#pragma unroll
            for (int r = 0; r < 4; ++r) acc[mi][nj][r] = 0.f;

    const int lr = tid >> 2;
    const int lc = (tid & 3) * 4;
    const int lkp = (tid & 3) * 2;
    const int NITER = K / GBK;

    float4 ra[2], rb[2];
#pragma unroll
    for (int it = 0; it < 2; ++it) {
        int row = lr + it * 64;
        int grow = bm + row;
        ra[it] = (grow < M) ? *(const float4*)(A + (size_t)grow * K + lc)
                            : make_float4(0.f, 0.f, 0.f, 0.f);
        rb[it] = *(const float4*)(B + (size_t)(bn + row) * K + lc);
    }
#pragma unroll
    for (int it = 0; it < 2; ++it) {
        int row = lr + it * 64;
        uint32_t h0, l0, h1, l1;
        bf16_split2(ra[it].x, ra[it].y, h0, l0);
        bf16_split2(ra[it].z, ra[it].w, h1, l1);
        Ah[SIDX(0, row, lkp)] = h0; Ah[SIDX(0, row, lkp + 1)] = h1;
        Al[SIDX(0, row, lkp)] = l0; Al[SIDX(0, row, lkp + 1)] = l1;
        bf16_split2(rb[it].x, rb[it].y, h0, l0);
        bf16_split2(rb[it].z, rb[it].w, h1, l1);
        Bh[SIDX(0, row, lkp)] = h0; Bh[SIDX(0, row, lkp + 1)] = h1;
        Bl[SIDX(0, row, lkp)] = l0; Bl[SIDX(0, row, lkp + 1)] = l1;
    }
    __syncthreads();

    for (int t = 0; t < NITER; ++t) {
        if (t + 1 < NITER) {
            int kb = (t + 1) * GBK;
#pragma unroll
            for (int it = 0; it < 2; ++it) {
                int row = lr + it * 64;
                int grow = bm + row;
                ra[it] = (grow < M)
                    ? *(const float4*)(A + (size_t)grow * K + kb + lc)
                    : make_float4(0.f, 0.f, 0.f, 0.f);
                rb[it] = *(const float4*)(B + (size_t)(bn + row) * K + kb + lc);
            }
        }

        const int buf = t & 1;
        uint32_t bhf[4][2], blf[4][2];
#pragma unroll
        for (int nj = 0; nj < 4; ++nj) {
            int row = wn + nj * 8 + g;
            bhf[nj][0] = Bh[SIDX(buf, row, tg)];
            bhf[nj][1] = Bh[SIDX(buf, row, tg + 4)];
            blf[nj][0] = Bl[SIDX(buf, row, tg)];
            blf[nj][1] = Bl[SIDX(buf, row, tg + 4)];
        }
#pragma unroll
        for (int mi = 0; mi < 4; ++mi) {
            int r0 = wm + mi * 16 + g;
            uint32_t ah0 = Ah[SIDX(buf, r0, tg)];
            uint32_t ah1 = Ah[SIDX(buf, r0 + 8, tg)];
            uint32_t ah2 = Ah[SIDX(buf, r0, tg + 4)];
            uint32_t ah3 = Ah[SIDX(buf, r0 + 8, tg + 4)];
            uint32_t al0 = Al[SIDX(buf, r0, tg)];
            uint32_t al1 = Al[SIDX(buf, r0 + 8, tg)];
            uint32_t al2 = Al[SIDX(buf, r0, tg + 4)];
            uint32_t al3 = Al[SIDX(buf, r0 + 8, tg + 4)];
#pragma unroll
            for (int nj = 0; nj < 4; ++nj) {
                MMA_BF16(acc[mi][nj], al0, al1, al2, al3, bhf[nj][0], bhf[nj][1]);
                MMA_BF16(acc[mi][nj], ah0, ah1, ah2, ah3, blf[nj][0], blf[nj][1]);
                MMA_BF16(acc[mi][nj], ah0, ah1, ah2, ah3, bhf[nj][0], bhf[nj][1]);
            }
        }

        if (t + 1 < NITER) {
            const int nb = (t + 1) & 1;
#pragma unroll
            for (int it = 0; it < 2; ++it) {
                int row = lr + it * 64;
                uint32_t h0, l0, h1, l1;
                bf16_split2(ra[it].x, ra[it].y, h0, l0);
                bf16_split2(ra[it].z, ra[it].w, h1, l1);
                Ah[SIDX(nb, row, lkp)] = h0; Ah[SIDX(nb, row, lkp + 1)] = h1;
                Al[SIDX(nb, row, lkp)] = l0; Al[SIDX(nb, row, lkp + 1)] = l1;
                bf16_split2(rb[it].x, rb[it].y, h0, l0);
                bf16_split2(rb[it].z, rb[it].w, h1, l1);
                Bh[SIDX(nb, row, lkp)] = h0; Bh[SIDX(nb, row, lkp + 1)] = h1;
                Bl[SIDX(nb, row, lkp)] = l0; Bl[SIDX(nb, row, lkp + 1)] = l1;
            }
            __syncthreads();
        }
    }

#pragma unroll
    for (int mi = 0; mi < 4; ++mi) {
        int row0 = bm + wm + mi * 16 + g;
#pragma unroll
        for (int nj = 0; nj < 4; ++nj) {
            int col = bn + wn + nj * 8 + tg * 2;
            if (row0 < M)
                *(float2*)&C[(size_t)row0 * HD + col] =
                    make_float2(acc[mi][nj][0], acc[mi][nj][1]);
            if (row0 + 8 < M)
                *(float2*)&C[(size_t)(row0 + 8) * HD + col] =
                    make_float2(acc[mi][nj][2], acc[mi][nj][3]);
        }
    }
}

// ------ fused edge logits: eval = leaky(ssrc[src] + srl_emb . v^T) ----------
// warp = 4 edges; 8 lanes/edge; sv reads are float4 (conflict-free: lane
// offset sl*16B spans one 128B wavefront; grp-lanes broadcast).
__global__ void __launch_bounds__(256) k_sfeat(const float* __restrict__ srl,
                                               const int* __restrict__ src) {
    __shared__ float sv[NH][FEAT];
    int tid = threadIdx.x;
#pragma unroll
    for (int i = tid; i < NH * FEAT; i += 256)
        ((float*)sv)[i] = g_vfeat[i];
    __syncthreads();

    int warp = tid >> 5, lane = tid & 31;
    int grp = lane >> 3, sl = lane & 7;
    int e = blockIdx.x * 32 + warp * 4 + grp;
    if (e >= NE) return;

    const float4* row = (const float4*)(srl + (size_t)e * FEAT);
    float acc[NH];
#pragma unroll
    for (int h = 0; h < NH; ++h) acc[h] = 0.f;
#pragma unroll
    for (int i = 0; i < 4; ++i) {
        float4 v = row[i * 8 + sl];
        int fb = (i * 8 + sl) * 4;
#pragma unroll
        for (int h = 0; h < NH; ++h) {
            float4 s = *(const float4*)&sv[h][fb];
            acc[h] += v.x * s.x + v.y * s.y + v.z * s.z + v.w * s.w;
        }
    }
    float ev = 0.f;
#pragma unroll
    for (int h = 0; h < NH; ++h) {
        float v = acc[h];
        v += __shfl_xor_sync(0xffffffffu, v, 1, 8);
        v += __shfl_xor_sync(0xffffffffu, v, 2, 8);
        v += __shfl_xor_sync(0xffffffffu, v, 4, 8);
        if (h == sl) ev = v;
    }
    int sid = __ldg(&src[e]);
    float x = g_ssrc[(size_t)sid * NH + sl] + ev;
    g_eval[(size_t)e * NH + sl] = (x > 0.f) ? x : 0.01f * x;
}

// ---------------- counting sort of edges by dst ----------------------------
__global__ void k_hist(const int* __restrict__ dst) {
    int t = blockIdx.x * blockDim.x + threadIdx.x;
    if (t < NE) atomicAdd(&g_counts[dst[t]], 1);
}

__global__ void __launch_bounds__(1024) k_scan() {
    __shared__ int sh[1024];
    int t = threadIdx.x;
    int base = t * 10;
    int local[10];
    int s = 0;
#pragma unroll
    for (int i = 0; i < 10; ++i) {
        int idx = base + i;
        int c = (idx < NP) ? g_counts[idx] : 0;
        local[i] = s;
        s += c;
    }
    sh[t] = s;
    __syncthreads();
    for (int off = 1; off < 1024; off <<= 1) {
        int v = (t >= off) ? sh[t - off] : 0;
        __syncthreads();
        sh[t] += v;
        __syncthreads();
    }
    int excl = sh[t] - s;
#pragma unroll
    for (int i = 0; i < 10; ++i) {
        int idx = base + i;
        if (idx < NP) {
            int o = excl + local[i];
            g_offsets[idx] = o;
            g_cursor[idx] = o;
        }
    }
}

__global__ void k_scatter(const int* __restrict__ dst,
                          const int* __restrict__ src) {
    int t = blockIdx.x * blockDim.x + threadIdx.x;
    if (t < NE) {
        int p = atomicAdd(&g_cursor[dst[t]], 1);
        g_edge_sorted[p] = t;
        g_src_sorted[p] = src[t];
    }
}

// -------- softmax weights per segment (off critical path) ------------------
__global__ void __launch_bounds__(256) k_alpha() {
    int p = blockIdx.x;
    int t = threadIdx.x;
    int h = t >> 5, lane = t & 31;
    int start = g_offsets[p];
    int cnt = g_counts[p];
    if (cnt == 0) return;

    float m = -3.0e38f;
    for (int i = lane; i < cnt; i += 32) {
        int eid = g_edge_sorted[start + i];
        m = fmaxf(m, g_eval[(size_t)eid * NH + h]);
    }
#pragma unroll
    for (int off = 16; off >= 1; off >>= 1)
        m = fmaxf(m, __shfl_xor_sync(0xffffffffu, m, off));

    float s = 0.f;
    for (int i = lane; i < cnt; i += 32) {
        int eid = g_edge_sorted[start + i];
        s += __expf(g_eval[(size_t)eid * NH + h] - m);
    }
#pragma unroll
    for (int off = 16; off >= 1; off >>= 1)
        s += __shfl_xor_sync(0xffffffffu, s, off);
    float inv = 1.f / s;

    for (int i = lane; i < cnt; i += 32) {
        int pos = start + i;
        int eid = g_edge_sorted[pos];
        g_alpha[(size_t)pos * NH + h] =
            __expf(g_eval[(size_t)eid * NH + h] - m) * inv;
    }
}

// -------- pure weighted gather over 128 output channels --------------------
__global__ void __launch_bounds__(128) k_gather(float* __restrict__ out,
                                                int colbase) {
    int p = blockIdx.x;
    int t = threadIdx.x;
    int ch = colbase + t;
    int start = g_offsets[p];
    int cnt = g_counts[p];
    int hh = ch >> 5;
    float acc = 0.f;
#pragma unroll 4
    for (int i = 0; i < cnt; ++i) {
        int pos = start + i;
        float a = __ldg(&g_alpha[(size_t)pos * NH + hh]);
        int sid = __ldg(&g_src_sorted[pos]);
        acc += a * __ldg(&g_z[(size_t)sid * HD + ch]);
    }
    out[(size_t)p * HD + ch] = acc;
}

// ---------------- launcher --------------------------------------------------
extern "C" void kernel_launch(void* const* d_in, const int* in_sizes, int n_in,
                              void* d_out, int out_size) {
    const float* h      = (const float*)d_in[0];
    const float* srl    = (const float*)d_in[1];
    const int*   src    = (const int*)d_in[2];
    const int*   dst    = (const int*)d_in[3];
    const float* W_fc   = (const float*)d_in[4];
    const float* W_feat = (const float*)d_in[5];
    const float* W_attn = (const float*)d_in[6];
    float* out = (float*)d_out;

    static cudaStream_t s1 = nullptr, s2 = nullptr;
    static cudaEvent_t ef = nullptr, ej2 = nullptr, ejA = nullptr,
                       eg0 = nullptr, ejg = nullptr;
    if (s1 == nullptr) {
        cudaStreamCreateWithFlags(&s1, cudaStreamNonBlocking);
        cudaStreamCreateWithFlags(&s2, cudaStreamNonBlocking);
        cudaEventCreateWithFlags(&ef,  cudaEventDisableTiming);
        cudaEventCreateWithFlags(&ej2, cudaEventDisableTiming);
        cudaEventCreateWithFlags(&ejA, cudaEventDisableTiming);
        cudaEventCreateWithFlags(&eg0, cudaEventDisableTiming);
        cudaEventCreateWithFlags(&ejg, cudaEventDisableTiming);
    }

    float* zptr;
    cudaGetSymbolAddress((void**)&zptr, g_z);

    // fork
    cudaEventRecord(ef, 0);
    cudaStreamWaitEvent(s1, ef, 0);
    cudaStreamWaitEvent(s2, ef, 0);

    // side chain 2: attention logits (independent of GEMM; combine fused)
    k_uvec<<<(NH * IN_DIM + 255) / 256, 256, 0, s2>>>(W_fc, W_attn);
    k_vfeat<<<(NH * FEAT + 255) / 256, 256, 0, s2>>>(W_feat, W_attn);
    k_ssrc2<<<(NA * 32 + 255) / 256, 256, 0, s2>>>(h);
    k_sfeat<<<(NE + 31) / 32, 256, 0, s2>>>(srl, src);
    cudaEventRecord(ej2, s2);

    // side chain 1: counting sort, then alpha (needs logits too)
    k_zero_counts<<<(NP + 255) / 256, 256, 0, s1>>>();
    k_hist<<<(NE + 255) / 256, 256, 0, s1>>>(dst);
    k_scan<<<1, 1024, 0, s1>>>();
    k_scatter<<<(NE + 255) / 256, 256, 0, s1>>>(dst, src);
    cudaStreamWaitEvent(s1, ej2, 0);
    k_alpha<<<NP, 256, 0, s1>>>();
    cudaEventRecord(ejA, s1);

    // main stream: GEMM halves (critical path)
    {
        int grid = (NA + GBM - 1) / GBM;   // 391
        k_gemm_bf16x2<<<grid, 256, GEMM_SMEM_BYTES>>>(h, W_fc, zptr, 0);
        cudaEventRecord(eg0, 0);
        k_gemm_bf16x2<<<grid, 256, GEMM_SMEM_BYTES>>>(h, W_fc, zptr, 128);
    }

    // gather cols 0-127 overlaps GEMM half 2 (on s2)
    cudaStreamWaitEvent(s2, eg0, 0);
    cudaStreamWaitEvent(s2, ejA, 0);
    k_gather<<<NP, 128, 0, s2>>>(out, 0);
    cudaEventRecord(ejg, s2);

    // gather cols 128-255 after GEMM half 2, then join
    cudaStreamWaitEvent(0, ejA, 0);
    k_gather<<<NP, 128>>>(out, 128);
    cudaStreamWaitEvent(0, ejg, 0);
}